// round 13
// baseline (speedup 1.0000x reference)
#include <cuda_runtime.h>
#include <math.h>

#define LSEQ 256
#define EDIM 768
#define HDIM 384
#define NDOM 9
#define BMAX 2048

// device scratch (no allocation allowed)
__device__ float g_feature[(size_t)BMAX * EDIM];   // [B, 2H]: [shared | specific]
__device__ float g_h1[(size_t)BMAX * 64];
__device__ float g_hdom[(size_t)BMAX * HDIM];
__device__ int   g_counts[16];
__device__ int   g_idx[NDOM * BMAX];

// ---------------------------------------------------------------------------
// K1: masked-attention pooling, warp-autonomous online softmax.
// 6 warps/CTA; warp w owns tokens w, w+6, ... entirely (lane l holds 24 cols:
// {4l+128j}). Score = 5-shfl warp reduce; NO block barrier in the main loop.
// Final 6-way state merge via smem (2 barriers total).
// ---------------------------------------------------------------------------
__global__ void __launch_bounds__(192) pool_kernel(
    const float* __restrict__ bert, const int* __restrict__ masks,
    const float* __restrict__ att_w, const float* __restrict__ att_b,
    float* __restrict__ pooled)
{
    const int b = blockIdx.x, tid = threadIdx.x;
    const int lane = tid & 31, w = tid >> 5;          // warp 0..5
    const float4* base = reinterpret_cast<const float4*>(bert + (size_t)b * LSEQ * EDIM);
    const int* mrow = masks + b * LSEQ;
    const float bb = att_b[0];

    float4 wv[6];
    #pragma unroll
    for (int j = 0; j < 6; ++j)
        wv[j] = reinterpret_cast<const float4*>(att_w)[lane + 32 * j];

    float4 acc[6];
    #pragma unroll
    for (int j = 0; j < 6; ++j) acc[j] = make_float4(0.f, 0.f, 0.f, 0.f);
    float m = -3e38f, d = 0.f;

    float4 x[6], xn[6];
    #pragma unroll
    for (int j = 0; j < 6; ++j) x[j] = base[(size_t)w * 192 + lane + 32 * j];

    for (int t = w; t < LSEQ; t += 6) {
        const int tn = t + 6;
        const bool more = (tn < LSEQ);
        if (more) {
            #pragma unroll
            for (int j = 0; j < 6; ++j)
                xn[j] = base[(size_t)tn * 192 + lane + 32 * j];
        }

        float p = 0.f;
        #pragma unroll
        for (int j = 0; j < 6; ++j)
            p += x[j].x * wv[j].x + x[j].y * wv[j].y
               + x[j].z * wv[j].z + x[j].w * wv[j].w;
        #pragma unroll
        for (int o = 16; o; o >>= 1) p += __shfl_xor_sync(0xffffffffu, p, o);

        float s = p + bb;
        if (mrow[t] == 0) s = -1e9f;

        const float nm = fmaxf(m, s);
        const float f  = __expf(m - nm);
        const float pe = __expf(s - nm);
        d = d * f + pe;
        #pragma unroll
        for (int j = 0; j < 6; ++j) {
            acc[j].x = acc[j].x * f + pe * x[j].x;
            acc[j].y = acc[j].y * f + pe * x[j].y;
            acc[j].z = acc[j].z * f + pe * x[j].z;
            acc[j].w = acc[j].w * f + pe * x[j].w;
        }
        m = nm;
        if (more) {
            #pragma unroll
            for (int j = 0; j < 6; ++j) x[j] = xn[j];
        }
    }

    // ---- merge 6 warp states (2 block barriers) ----
    __shared__ float sm_m[6], sm_d[6];
    __shared__ float sacc[6][EDIM];      // 18 KB

    if (lane == 0) sm_m[w] = m;
    __syncthreads();
    float M = sm_m[0];
    #pragma unroll
    for (int i = 1; i < 6; ++i) M = fmaxf(M, sm_m[i]);
    const float fw = __expf(m - M);      // uniform within warp
    if (lane == 0) sm_d[w] = d * fw;
    #pragma unroll
    for (int j = 0; j < 6; ++j) {
        float4 v;
        v.x = acc[j].x * fw; v.y = acc[j].y * fw;
        v.z = acc[j].z * fw; v.w = acc[j].w * fw;
        reinterpret_cast<float4*>(&sacc[w][0])[lane + 32 * j] = v;
    }
    __syncthreads();

    const float D = sm_d[0] + sm_d[1] + sm_d[2] + sm_d[3] + sm_d[4] + sm_d[5];
    const float inv = 1.f / D;
    float4 o = make_float4(0.f, 0.f, 0.f, 0.f);
    #pragma unroll
    for (int ww = 0; ww < 6; ++ww) {
        float4 v = reinterpret_cast<const float4*>(&sacc[ww][0])[tid];
        o.x += v.x; o.y += v.y; o.z += v.z; o.w += v.w;
    }
    o.x *= inv; o.y *= inv; o.z *= inv; o.w *= inv;
    reinterpret_cast<float4*>(pooled + (size_t)b * EDIM)[tid] = o;
}

// ---------------------------------------------------------------------------
// category routing lists
// ---------------------------------------------------------------------------
__global__ void zero_counts_kernel() { if (threadIdx.x < 16) g_counts[threadIdx.x] = 0; }

__global__ void scatter_kernel(const int* __restrict__ category, int B) {
    int i = blockIdx.x * blockDim.x + threadIdx.x;
    if (i < B) {
        int c = category[i];
        int p = atomicAdd(&g_counts[c], 1);
        g_idx[c * BMAX + p] = i;
    }
}

// ---------------------------------------------------------------------------
// tf32 helpers (3xTF32 compensated; numerics proven)
// ---------------------------------------------------------------------------
__device__ __forceinline__ float tf32_trunc(float v) {
    return __uint_as_float(__float_as_uint(v) & 0xFFFFE000u);
}

__device__ __forceinline__ void mma_tf32(float* c,
    float a0, float a1, float a2, float a3, float b0, float b1)
{
    asm volatile(
        "mma.sync.aligned.m16n8k8.row.col.f32.tf32.tf32.f32 "
        "{%0,%1,%2,%3}, {%4,%5,%6,%7}, {%8,%9}, {%0,%1,%2,%3};\n"
        : "+f"(c[0]), "+f"(c[1]), "+f"(c[2]), "+f"(c[3])
        : "r"(__float_as_uint(a0)), "r"(__float_as_uint(a1)),
          "r"(__float_as_uint(a2)), "r"(__float_as_uint(a3)),
          "r"(__float_as_uint(b0)), "r"(__float_as_uint(b1)));
}

// ---------------------------------------------------------------------------
// Generic DENSE 64x64 3xTF32 GEMM tile (proven; used by fusedA/fusedB).
// ---------------------------------------------------------------------------
__device__ __forceinline__ void mma_gemm64_tile(
    const float* __restrict__ A, int lda,
    const float* __restrict__ W, int ldw,
    const float* __restrict__ bias,
    float* __restrict__ C, int ldc,
    int M, int K, int mt, int colbase,
    float (*As)[16][68], float (*Bs)[16][68])
{
    const int t = threadIdx.x;
    const int lane = t & 31, wid = t >> 5;
    const int warp_m = wid & 3, warp_n = wid >> 2;
    const int gid = lane >> 2, tig = lane & 3;

    const int arow = t >> 2, akk = (t & 3) * 4;
    const int bk = t >> 4, bn = (t & 15) * 4;

    const int ga = mt * 64 + arow;
    const bool aload = (ga < M);
    const float* Ap = A + (size_t)(aload ? ga : 0) * lda;

    float acc[4][4];
    #pragma unroll
    for (int i = 0; i < 4; ++i)
        #pragma unroll
        for (int j = 0; j < 4; ++j) acc[i][j] = 0.f;

    const int NS = K / 16;
    float4 av = make_float4(0.f, 0.f, 0.f, 0.f);
    if (aload) av = *reinterpret_cast<const float4*>(Ap + akk);
    float4 bv = *reinterpret_cast<const float4*>(W + (size_t)bk * ldw + colbase + bn);
    As[0][akk + 0][arow] = av.x; As[0][akk + 1][arow] = av.y;
    As[0][akk + 2][arow] = av.z; As[0][akk + 3][arow] = av.w;
    *reinterpret_cast<float4*>(&Bs[0][bk][bn]) = bv;
    __syncthreads();

    const int am = warp_m * 16;
    const int bn0 = warp_n * 32;

    for (int s = 0; s < NS; ++s) {
        const int cur = s & 1;
        float4 av2 = make_float4(0.f, 0.f, 0.f, 0.f), bv2;
        if (s + 1 < NS) {
            const int k0 = (s + 1) * 16;
            if (aload) av2 = *reinterpret_cast<const float4*>(Ap + k0 + akk);
            bv2 = *reinterpret_cast<const float4*>(W + (size_t)(k0 + bk) * ldw + colbase + bn);
        }

        #pragma unroll
        for (int g = 0; g < 2; ++g) {
            const int ka = g * 8;
            float a0 = As[cur][ka + tig][am + gid];
            float a1 = As[cur][ka + tig][am + gid + 8];
            float a2 = As[cur][ka + tig + 4][am + gid];
            float a3 = As[cur][ka + tig + 4][am + gid + 8];
            float ah0 = tf32_trunc(a0), al0 = tf32_trunc(a0 - ah0);
            float ah1 = tf32_trunc(a1), al1 = tf32_trunc(a1 - ah1);
            float ah2 = tf32_trunc(a2), al2 = tf32_trunc(a2 - ah2);
            float ah3 = tf32_trunc(a3), al3 = tf32_trunc(a3 - ah3);
            #pragma unroll
            for (int nt = 0; nt < 4; ++nt) {
                const int bcol = bn0 + nt * 8 + gid;
                float b0 = Bs[cur][ka + tig][bcol];
                float b1 = Bs[cur][ka + tig + 4][bcol];
                float bh0 = tf32_trunc(b0), bl0 = tf32_trunc(b0 - bh0);
                float bh1 = tf32_trunc(b1), bl1 = tf32_trunc(b1 - bh1);
                mma_tf32(acc[nt], ah0, ah1, ah2, ah3, bh0, bh1);
                mma_tf32(acc[nt], ah0, ah1, ah2, ah3, bl0, bl1);
                mma_tf32(acc[nt], al0, al1, al2, al3, bh0, bh1);
            }
        }

        if (s + 1 < NS) {
            const int nb = cur ^ 1;
            As[nb][akk + 0][arow] = av2.x; As[nb][akk + 1][arow] = av2.y;
            As[nb][akk + 2][arow] = av2.z; As[nb][akk + 3][arow] = av2.w;
            *reinterpret_cast<float4*>(&Bs[nb][bk][bn]) = bv2;
        }
        __syncthreads();
    }

    const int r0 = mt * 64 + am + gid;
    const int r1 = r0 + 8;
    #pragma unroll
    for (int nt = 0; nt < 4; ++nt) {
        const int cn = bn0 + nt * 8 + 2 * tig;
        const float bb0 = bias[colbase + cn];
        const float bb1 = bias[colbase + cn + 1];
        if (r0 < M) {
            float2 o;
            o.x = fmaxf(acc[nt][0] + bb0, 0.f);
            o.y = fmaxf(acc[nt][1] + bb1, 0.f);
            *reinterpret_cast<float2*>(&C[(size_t)r0 * ldc + colbase + cn]) = o;
        }
        if (r1 < M) {
            float2 o;
            o.x = fmaxf(acc[nt][2] + bb0, 0.f);
            o.y = fmaxf(acc[nt][3] + bb1, 0.f);
            *reinterpret_cast<float2*>(&C[(size_t)r1 * ldc + colbase + cn]) = o;
        }
    }
}

// ---------------------------------------------------------------------------
// Expert + shared MLP, 3xTF32 with 32x64 tiles (R12-proven).
// ---------------------------------------------------------------------------
__global__ void __launch_bounds__(256) expert_mma_kernel(
    const float* __restrict__ pooled,
    const float* __restrict__ Wsh, const float* __restrict__ bsh,
    const float* __restrict__ Wsp, const float* __restrict__ bsp,
    int B)
{
    const int c = blockIdx.z;
    const bool dense = (c == NDOM);
    const int cnt = dense ? B : g_counts[c];
    const int mt = blockIdx.y;
    if (mt * 32 >= cnt) return;

    const float* W    = dense ? Wsh : (Wsp + (size_t)c * EDIM * HDIM);
    const float* bias = dense ? bsh : (bsp + c * HDIM);
    const int colbase = blockIdx.x * 64;
    const int outcol  = (dense ? 0 : HDIM) + colbase;

    __shared__ float As[2][16][36];
    __shared__ float Bs[2][16][68];

    const int t = threadIdx.x;
    const int lane = t & 31, wid = t >> 5;
    const int warp_m = wid & 1, warp_n = wid >> 1;
    const int gid = lane >> 2, tig = lane & 3;

    const int arow = t >> 2, akk = (t & 3) * 4;
    const bool athr = (t < 128);
    const int bk = t >> 4, bn = (t & 15) * 4;

    int gi = -1;
    if (athr) {
        const int amrow = mt * 32 + arow;
        if (amrow < cnt) gi = dense ? amrow : g_idx[c * BMAX + amrow];
    }
    const float* Ap = pooled + (size_t)(gi >= 0 ? gi : 0) * EDIM;

    float acc[2][4];
    #pragma unroll
    for (int i = 0; i < 2; ++i)
        #pragma unroll
        for (int j = 0; j < 4; ++j) acc[i][j] = 0.f;

    const int NS = EDIM / 16;
    float4 av = make_float4(0.f, 0.f, 0.f, 0.f);
    if (gi >= 0) av = *reinterpret_cast<const float4*>(Ap + akk);
    float4 bv = *reinterpret_cast<const float4*>(W + (size_t)bk * HDIM + colbase + bn);
    if (athr) {
        As[0][akk + 0][arow] = av.x; As[0][akk + 1][arow] = av.y;
        As[0][akk + 2][arow] = av.z; As[0][akk + 3][arow] = av.w;
    }
    *reinterpret_cast<float4*>(&Bs[0][bk][bn]) = bv;
    __syncthreads();

    const int am = warp_m * 16;
    const int bn0 = warp_n * 16;

    for (int s = 0; s < NS; ++s) {
        const int cur = s & 1;
        float4 av2 = make_float4(0.f, 0.f, 0.f, 0.f), bv2;
        if (s + 1 < NS) {
            const int k0 = (s + 1) * 16;
            if (gi >= 0) av2 = *reinterpret_cast<const float4*>(Ap + k0 + akk);
            bv2 = *reinterpret_cast<const float4*>(W + (size_t)(k0 + bk) * HDIM + colbase + bn);
        }

        #pragma unroll
        for (int g = 0; g < 2; ++g) {
            const int ka = g * 8;
            float a0 = As[cur][ka + tig][am + gid];
            float a1 = As[cur][ka + tig][am + gid + 8];
            float a2 = As[cur][ka + tig + 4][am + gid];
            float a3 = As[cur][ka + tig + 4][am + gid + 8];
            float ah0 = tf32_trunc(a0), al0 = tf32_trunc(a0 - ah0);
            float ah1 = tf32_trunc(a1), al1 = tf32_trunc(a1 - ah1);
            float ah2 = tf32_trunc(a2), al2 = tf32_trunc(a2 - ah2);
            float ah3 = tf32_trunc(a3), al3 = tf32_trunc(a3 - ah3);
            #pragma unroll
            for (int nt = 0; nt < 2; ++nt) {
                const int bcol = bn0 + nt * 8 + gid;
                float b0 = Bs[cur][ka + tig][bcol];
                float b1 = Bs[cur][ka + tig + 4][bcol];
                float bh0 = tf32_trunc(b0), bl0 = tf32_trunc(b0 - bh0);
                float bh1 = tf32_trunc(b1), bl1 = tf32_trunc(b1 - bh1);
                mma_tf32(acc[nt], ah0, ah1, ah2, ah3, bh0, bh1);
                mma_tf32(acc[nt], ah0, ah1, ah2, ah3, bl0, bl1);
                mma_tf32(acc[nt], al0, al1, al2, al3, bh0, bh1);
            }
        }

        if (s + 1 < NS) {
            const int nb = cur ^ 1;
            if (athr) {
                As[nb][akk + 0][arow] = av2.x; As[nb][akk + 1][arow] = av2.y;
                As[nb][akk + 2][arow] = av2.z; As[nb][akk + 3][arow] = av2.w;
            }
            *reinterpret_cast<float4*>(&Bs[nb][bk][bn]) = bv2;
        }
        __syncthreads();
    }

    const int r0 = mt * 32 + am + gid;
    const int r1 = r0 + 8;
    int ridx0 = 0, ridx1 = 0;
    const bool v0 = (r0 < cnt), v1 = (r1 < cnt);
    if (v0) ridx0 = dense ? r0 : g_idx[c * BMAX + r0];
    if (v1) ridx1 = dense ? r1 : g_idx[c * BMAX + r1];

    #pragma unroll
    for (int nt = 0; nt < 2; ++nt) {
        const int cn = bn0 + nt * 8 + 2 * tig;
        const float bb0 = bias[colbase + cn];
        const float bb1 = bias[colbase + cn + 1];
        if (v0) {
            float2 o;
            o.x = fmaxf(acc[nt][0] + bb0, 0.f);
            o.y = fmaxf(acc[nt][1] + bb1, 0.f);
            *reinterpret_cast<float2*>(&g_feature[(size_t)ridx0 * EDIM + outcol + cn]) = o;
        }
        if (v1) {
            float2 o;
            o.x = fmaxf(acc[nt][2] + bb0, 0.f);
            o.y = fmaxf(acc[nt][3] + bb1, 0.f);
            *reinterpret_cast<float2*>(&g_feature[(size_t)ridx1 * EDIM + outcol + cn]) = o;
        }
    }
}

// ---------------------------------------------------------------------------
// fusedA: dec1 (32 mma tiles) + domain1 (192 mma tiles) + cls (warp/sample)
// ---------------------------------------------------------------------------
#define FA_DEC1 32
#define FA_DOM1 (FA_DEC1 + 192)
__global__ void __launch_bounds__(256) fusedA_kernel(
    const float* __restrict__ Wd1, const float* __restrict__ bd1,
    const float* __restrict__ Wdo1, const float* __restrict__ bdo1,
    const float* __restrict__ Wc, const float* __restrict__ bc,
    float* __restrict__ out, int B)
{
    __shared__ float As[2][16][68];
    __shared__ float Bs[2][16][68];
    const int bx = blockIdx.x;

    if (bx < FA_DEC1) {
        mma_gemm64_tile(g_feature, EDIM, Wd1, 64, bd1, g_h1, 64, B, EDIM,
                        bx, 0, As, Bs);
    } else if (bx < FA_DOM1) {
        const int idx = bx - FA_DEC1;
        mma_gemm64_tile(g_feature, EDIM, Wdo1, HDIM, bdo1, g_hdom, HDIM, B, HDIM,
                        idx / 6, (idx % 6) * 64, As, Bs);
    } else {
        const int sample = (bx - FA_DOM1) * 8 + (threadIdx.x >> 5);
        const int lane = threadIdx.x & 31;
        if (sample < B) {
            const float4* f = reinterpret_cast<const float4*>(g_feature + (size_t)sample * EDIM);
            const float4* wc = reinterpret_cast<const float4*>(Wc);
            float acc = 0.f;
            #pragma unroll
            for (int i = 0; i < 6; ++i) {
                float4 a = f[lane + 32 * i], ww = wc[lane + 32 * i];
                acc += a.x * ww.x + a.y * ww.y + a.z * ww.z + a.w * ww.w;
            }
            #pragma unroll
            for (int o = 16; o; o >>= 1) acc += __shfl_xor_sync(0xffffffffu, acc, o);
            if (lane == 0) out[sample] = 1.f / (1.f + __expf(-(acc + bc[0])));
        }
    }
}

// ---------------------------------------------------------------------------
// fusedB: dec2 (384 mma tiles) + domain2 (warp/sample)
// ---------------------------------------------------------------------------
#define FB_DEC2 384
__global__ void __launch_bounds__(256) fusedB_kernel(
    const float* __restrict__ Wd2, const float* __restrict__ bd2,
    const float* __restrict__ Wdo2, const float* __restrict__ bdo2,
    float* __restrict__ rec, float* __restrict__ dp, int B)
{
    __shared__ float As[2][16][68];
    __shared__ float Bs[2][16][68];
    const int bx = blockIdx.x;

    if (bx < FB_DEC2) {
        mma_gemm64_tile(g_h1, 64, Wd2, EDIM, bd2, rec, EDIM, B, 64,
                        bx / 12, (bx % 12) * 64, As, Bs);
    } else {
        const int sample = (bx - FB_DEC2) * 8 + (threadIdx.x >> 5);
        const int lane = threadIdx.x & 31;
        if (sample < B) {
            const float* h = g_hdom + (size_t)sample * HDIM;
            float a[NDOM];
            #pragma unroll
            for (int j = 0; j < NDOM; ++j) a[j] = 0.f;
            #pragma unroll
            for (int i = 0; i < 3; ++i) {
                const int k = (lane + 32 * i) * 4;
                float4 hv = *reinterpret_cast<const float4*>(h + k);
                float hh[4] = {hv.x, hv.y, hv.z, hv.w};
                #pragma unroll
                for (int q = 0; q < 4; ++q) {
                    const float* wrow = Wdo2 + (k + q) * NDOM;
                    #pragma unroll
                    for (int j = 0; j < NDOM; ++j) a[j] += hh[q] * wrow[j];
                }
            }
            #pragma unroll
            for (int j = 0; j < NDOM; ++j) {
                #pragma unroll
                for (int o = 16; o; o >>= 1) a[j] += __shfl_xor_sync(0xffffffffu, a[j], o);
            }
            if (lane == 0) {
                #pragma unroll
                for (int j = 0; j < NDOM; ++j)
                    dp[(size_t)sample * NDOM + j] = a[j] + bdo2[j];
            }
        }
    }
}

// ---------------------------------------------------------------------------
extern "C" void kernel_launch(void* const* d_in, const int* in_sizes, int n_in,
                              void* d_out, int out_size)
{
    const float* bert     = (const float*)d_in[0];
    const int*   masks    = (const int*)d_in[1];
    const int*   category = (const int*)d_in[2];
    const float* att_w = (const float*)d_in[4];
    const float* att_b = (const float*)d_in[5];
    const float* Wsh = (const float*)d_in[6];  const float* bsh = (const float*)d_in[7];
    const float* Wsp = (const float*)d_in[8];  const float* bsp = (const float*)d_in[9];
    const float* Wd1 = (const float*)d_in[10]; const float* bd1 = (const float*)d_in[11];
    const float* Wd2 = (const float*)d_in[12]; const float* bd2 = (const float*)d_in[13];
    const float* Wc  = (const float*)d_in[14]; const float* bc  = (const float*)d_in[15];
    const float* Wdo1 = (const float*)d_in[16]; const float* bdo1 = (const float*)d_in[17];
    const float* Wdo2 = (const float*)d_in[18]; const float* bdo2 = (const float*)d_in[19];

    const int B = in_sizes[2];

    float* out    = (float*)d_out;
    float* rec    = out + B;
    float* pooled = rec + (size_t)B * EDIM;
    float* dp     = pooled + (size_t)B * EDIM;

    // routing lists (off the data critical path)
    zero_counts_kernel<<<1, 16>>>();
    scatter_kernel<<<(B + 255) / 256, 256>>>(category, B);

    pool_kernel<<<B, 192>>>(bert, masks, att_w, att_b, pooled);

    // shared MLP (slab 9) + 9 specific experts: 3xTF32, 32-row tiles
    expert_mma_kernel<<<dim3(HDIM / 64, (B + 31) / 32, NDOM + 1), 256>>>(
        pooled, Wsh, bsh, Wsp, bsp, B);

    // fusedA: dec1 + domain1 + cls (all read g_feature)
    fusedA_kernel<<<FA_DOM1 + (B + 7) / 8, 256>>>(
        Wd1, bd1, Wdo1, bdo1, Wc, bc, out, B);

    // fusedB: dec2 + domain2
    fusedB_kernel<<<FB_DEC2 + (B + 7) / 8, 256>>>(
        Wd2, bd2, Wdo2, bdo2, rec, dp, B);
}

// round 14
// speedup vs baseline: 1.3135x; 1.3135x over previous
#include <cuda_runtime.h>
#include <math.h>

#define LSEQ 256
#define EDIM 768
#define HDIM 384
#define NDOM 9
#define BMAX 2048
#define PT 8

// device scratch (no allocation allowed)
__device__ float g_feature[(size_t)BMAX * EDIM];   // [B, 2H]: [shared | specific]
__device__ float g_h1[(size_t)BMAX * 64];
__device__ float g_hdom[(size_t)BMAX * HDIM];
__device__ int   g_counts[16];
__device__ int   g_idx[NDOM * BMAX];

// ---------------------------------------------------------------------------
// K1: fused masked-attention pooling, chunked online softmax (R12-proven).
// ---------------------------------------------------------------------------
__global__ void __launch_bounds__(192) pool_kernel(
    const float* __restrict__ bert, const int* __restrict__ masks,
    const float* __restrict__ att_w, const float* __restrict__ att_b,
    float* __restrict__ pooled)
{
    const int b = blockIdx.x, tid = threadIdx.x;
    const int lane = tid & 31, wid = tid >> 5;
    const float4* base = reinterpret_cast<const float4*>(bert + (size_t)b * LSEQ * EDIM);
    const float4 w = reinterpret_cast<const float4*>(att_w)[tid];
    const float bb = att_b[0];

    __shared__ float wr[2][PT][8];
    __shared__ int msk[LSEQ];
    for (int i = tid; i < LSEQ; i += 192) msk[i] = masks[b * LSEQ + i];

    float4 acc = make_float4(0.f, 0.f, 0.f, 0.f);
    float m = -3e38f, d = 0.f;

    float4 x[PT], xn[PT];
    #pragma unroll
    for (int j = 0; j < PT; ++j) x[j] = base[j * 192 + tid];
    __syncthreads();

    const int NC = LSEQ / PT;
    for (int c = 0; c < NC; ++c) {
        const int cb = c & 1;
        float p[PT];
        #pragma unroll
        for (int j = 0; j < PT; ++j)
            p[j] = x[j].x * w.x + x[j].y * w.y + x[j].z * w.z + x[j].w * w.w;

        if (c + 1 < NC) {
            #pragma unroll
            for (int j = 0; j < PT; ++j)
                xn[j] = base[((c + 1) * PT + j) * 192 + tid];
        }

        #pragma unroll
        for (int j = 0; j < PT; ++j) {
            #pragma unroll
            for (int o = 16; o; o >>= 1)
                p[j] += __shfl_xor_sync(0xffffffffu, p[j], o);
        }
        if (lane == 0) {
            #pragma unroll
            for (int j = 0; j < PT; ++j) wr[cb][j][wid] = p[j];
        }
        __syncthreads();

        float s[PT], Mc = -3e38f;
        #pragma unroll
        for (int j = 0; j < PT; ++j) {
            s[j] = wr[cb][j][0] + wr[cb][j][1] + wr[cb][j][2]
                 + wr[cb][j][3] + wr[cb][j][4] + wr[cb][j][5] + bb;
            if (msk[c * PT + j] == 0) s[j] = -1e9f;
            Mc = fmaxf(Mc, s[j]);
        }
        float pe[PT], dc = 0.f;
        #pragma unroll
        for (int j = 0; j < PT; ++j) { pe[j] = __expf(s[j] - Mc); dc += pe[j]; }
        float4 ca = make_float4(0.f, 0.f, 0.f, 0.f);
        #pragma unroll
        for (int j = 0; j < PT; ++j) {
            ca.x += pe[j] * x[j].x; ca.y += pe[j] * x[j].y;
            ca.z += pe[j] * x[j].z; ca.w += pe[j] * x[j].w;
        }
        const float nm = fmaxf(m, Mc);
        const float fo = __expf(m - nm), fn = __expf(Mc - nm);
        d = d * fo + dc * fn;
        acc.x = acc.x * fo + ca.x * fn;
        acc.y = acc.y * fo + ca.y * fn;
        acc.z = acc.z * fo + ca.z * fn;
        acc.w = acc.w * fo + ca.w * fn;
        m = nm;
        #pragma unroll
        for (int j = 0; j < PT; ++j) x[j] = xn[j];
    }
    const float inv = 1.f / d;
    float4 o = make_float4(acc.x * inv, acc.y * inv, acc.z * inv, acc.w * inv);
    reinterpret_cast<float4*>(pooled + (size_t)b * EDIM)[tid] = o;
}

// ---------------------------------------------------------------------------
// category routing lists
// ---------------------------------------------------------------------------
__global__ void zero_counts_kernel() { if (threadIdx.x < 16) g_counts[threadIdx.x] = 0; }

__global__ void scatter_kernel(const int* __restrict__ category, int B) {
    int i = blockIdx.x * blockDim.x + threadIdx.x;
    if (i < B) {
        int c = category[i];
        int p = atomicAdd(&g_counts[c], 1);
        g_idx[c * BMAX + p] = i;
    }
}

// ---------------------------------------------------------------------------
// tf32 helpers (3xTF32 compensated; numerics proven)
// ---------------------------------------------------------------------------
__device__ __forceinline__ float tf32_trunc(float v) {
    return __uint_as_float(__float_as_uint(v) & 0xFFFFE000u);
}

__device__ __forceinline__ void mma_tf32(float* c,
    float a0, float a1, float a2, float a3, float b0, float b1)
{
    asm volatile(
        "mma.sync.aligned.m16n8k8.row.col.f32.tf32.tf32.f32 "
        "{%0,%1,%2,%3}, {%4,%5,%6,%7}, {%8,%9}, {%0,%1,%2,%3};\n"
        : "+f"(c[0]), "+f"(c[1]), "+f"(c[2]), "+f"(c[3])
        : "r"(__float_as_uint(a0)), "r"(__float_as_uint(a1)),
          "r"(__float_as_uint(a2)), "r"(__float_as_uint(a3)),
          "r"(__float_as_uint(b0)), "r"(__float_as_uint(b1)));
}

// ---------------------------------------------------------------------------
// Generic DENSE 64x64 3xTF32 GEMM tile (proven).
// ---------------------------------------------------------------------------
__device__ __forceinline__ void mma_gemm64_tile(
    const float* __restrict__ A, int lda,
    const float* __restrict__ W, int ldw,
    const float* __restrict__ bias,
    float* __restrict__ C, int ldc,
    int M, int K, int mt, int colbase,
    float (*As)[16][68], float (*Bs)[16][68])
{
    const int t = threadIdx.x;
    const int lane = t & 31, wid = t >> 5;
    const int warp_m = wid & 3, warp_n = wid >> 2;
    const int gid = lane >> 2, tig = lane & 3;

    const int arow = t >> 2, akk = (t & 3) * 4;
    const int bk = t >> 4, bn = (t & 15) * 4;

    const int ga = mt * 64 + arow;
    const bool aload = (ga < M);
    const float* Ap = A + (size_t)(aload ? ga : 0) * lda;

    float acc[4][4];
    #pragma unroll
    for (int i = 0; i < 4; ++i)
        #pragma unroll
        for (int j = 0; j < 4; ++j) acc[i][j] = 0.f;

    const int NS = K / 16;
    float4 av = make_float4(0.f, 0.f, 0.f, 0.f);
    if (aload) av = *reinterpret_cast<const float4*>(Ap + akk);
    float4 bv = *reinterpret_cast<const float4*>(W + (size_t)bk * ldw + colbase + bn);
    As[0][akk + 0][arow] = av.x; As[0][akk + 1][arow] = av.y;
    As[0][akk + 2][arow] = av.z; As[0][akk + 3][arow] = av.w;
    *reinterpret_cast<float4*>(&Bs[0][bk][bn]) = bv;
    __syncthreads();

    const int am = warp_m * 16;
    const int bn0 = warp_n * 32;

    for (int s = 0; s < NS; ++s) {
        const int cur = s & 1;
        float4 av2 = make_float4(0.f, 0.f, 0.f, 0.f), bv2;
        if (s + 1 < NS) {
            const int k0 = (s + 1) * 16;
            if (aload) av2 = *reinterpret_cast<const float4*>(Ap + k0 + akk);
            bv2 = *reinterpret_cast<const float4*>(W + (size_t)(k0 + bk) * ldw + colbase + bn);
        }

        #pragma unroll
        for (int g = 0; g < 2; ++g) {
            const int ka = g * 8;
            float a0 = As[cur][ka + tig][am + gid];
            float a1 = As[cur][ka + tig][am + gid + 8];
            float a2 = As[cur][ka + tig + 4][am + gid];
            float a3 = As[cur][ka + tig + 4][am + gid + 8];
            float ah0 = tf32_trunc(a0), al0 = tf32_trunc(a0 - ah0);
            float ah1 = tf32_trunc(a1), al1 = tf32_trunc(a1 - ah1);
            float ah2 = tf32_trunc(a2), al2 = tf32_trunc(a2 - ah2);
            float ah3 = tf32_trunc(a3), al3 = tf32_trunc(a3 - ah3);
            #pragma unroll
            for (int nt = 0; nt < 4; ++nt) {
                const int bcol = bn0 + nt * 8 + gid;
                float b0 = Bs[cur][ka + tig][bcol];
                float b1 = Bs[cur][ka + tig + 4][bcol];
                float bh0 = tf32_trunc(b0), bl0 = tf32_trunc(b0 - bh0);
                float bh1 = tf32_trunc(b1), bl1 = tf32_trunc(b1 - bh1);
                mma_tf32(acc[nt], ah0, ah1, ah2, ah3, bh0, bh1);
                mma_tf32(acc[nt], ah0, ah1, ah2, ah3, bl0, bl1);
                mma_tf32(acc[nt], al0, al1, al2, al3, bh0, bh1);
            }
        }

        if (s + 1 < NS) {
            const int nb = cur ^ 1;
            As[nb][akk + 0][arow] = av2.x; As[nb][akk + 1][arow] = av2.y;
            As[nb][akk + 2][arow] = av2.z; As[nb][akk + 3][arow] = av2.w;
            *reinterpret_cast<float4*>(&Bs[nb][bk][bn]) = bv2;
        }
        __syncthreads();
    }

    const int r0 = mt * 64 + am + gid;
    const int r1 = r0 + 8;
    #pragma unroll
    for (int nt = 0; nt < 4; ++nt) {
        const int cn = bn0 + nt * 8 + 2 * tig;
        const float bb0 = bias[colbase + cn];
        const float bb1 = bias[colbase + cn + 1];
        if (r0 < M) {
            float2 o;
            o.x = fmaxf(acc[nt][0] + bb0, 0.f);
            o.y = fmaxf(acc[nt][1] + bb1, 0.f);
            *reinterpret_cast<float2*>(&C[(size_t)r0 * ldc + colbase + cn]) = o;
        }
        if (r1 < M) {
            float2 o;
            o.x = fmaxf(acc[nt][2] + bb0, 0.f);
            o.y = fmaxf(acc[nt][3] + bb1, 0.f);
            *reinterpret_cast<float2*>(&C[(size_t)r1 * ldc + colbase + cn]) = o;
        }
    }
}

// ---------------------------------------------------------------------------
// Specific experts only, 3xTF32, 32x64 tiles (R12-proven body).
// blockIdx.z = category 0..8. Writes g_feature[:, HDIM:2H).
// ---------------------------------------------------------------------------
__global__ void __launch_bounds__(256) expert_mma_kernel(
    const float* __restrict__ pooled,
    const float* __restrict__ Wsp, const float* __restrict__ bsp)
{
    const int c = blockIdx.z;
    const int cnt = g_counts[c];
    const int mt = blockIdx.y;
    if (mt * 32 >= cnt) return;

    const float* W    = Wsp + (size_t)c * EDIM * HDIM;
    const float* bias = bsp + c * HDIM;
    const int colbase = blockIdx.x * 64;
    const int outcol  = HDIM + colbase;

    __shared__ float As[2][16][36];
    __shared__ float Bs[2][16][68];

    const int t = threadIdx.x;
    const int lane = t & 31, wid = t >> 5;
    const int warp_m = wid & 1, warp_n = wid >> 1;
    const int gid = lane >> 2, tig = lane & 3;

    const int arow = t >> 2, akk = (t & 3) * 4;
    const bool athr = (t < 128);
    const int bk = t >> 4, bn = (t & 15) * 4;

    int gi = -1;
    if (athr) {
        const int amrow = mt * 32 + arow;
        if (amrow < cnt) gi = g_idx[c * BMAX + amrow];
    }
    const float* Ap = pooled + (size_t)(gi >= 0 ? gi : 0) * EDIM;

    float acc[2][4];
    #pragma unroll
    for (int i = 0; i < 2; ++i)
        #pragma unroll
        for (int j = 0; j < 4; ++j) acc[i][j] = 0.f;

    const int NS = EDIM / 16;
    float4 av = make_float4(0.f, 0.f, 0.f, 0.f);
    if (gi >= 0) av = *reinterpret_cast<const float4*>(Ap + akk);
    float4 bv = *reinterpret_cast<const float4*>(W + (size_t)bk * HDIM + colbase + bn);
    if (athr) {
        As[0][akk + 0][arow] = av.x; As[0][akk + 1][arow] = av.y;
        As[0][akk + 2][arow] = av.z; As[0][akk + 3][arow] = av.w;
    }
    *reinterpret_cast<float4*>(&Bs[0][bk][bn]) = bv;
    __syncthreads();

    const int am = warp_m * 16;
    const int bn0 = warp_n * 16;

    for (int s = 0; s < NS; ++s) {
        const int cur = s & 1;
        float4 av2 = make_float4(0.f, 0.f, 0.f, 0.f), bv2;
        if (s + 1 < NS) {
            const int k0 = (s + 1) * 16;
            if (gi >= 0) av2 = *reinterpret_cast<const float4*>(Ap + k0 + akk);
            bv2 = *reinterpret_cast<const float4*>(W + (size_t)(k0 + bk) * HDIM + colbase + bn);
        }

        #pragma unroll
        for (int g = 0; g < 2; ++g) {
            const int ka = g * 8;
            float a0 = As[cur][ka + tig][am + gid];
            float a1 = As[cur][ka + tig][am + gid + 8];
            float a2 = As[cur][ka + tig + 4][am + gid];
            float a3 = As[cur][ka + tig + 4][am + gid + 8];
            float ah0 = tf32_trunc(a0), al0 = tf32_trunc(a0 - ah0);
            float ah1 = tf32_trunc(a1), al1 = tf32_trunc(a1 - ah1);
            float ah2 = tf32_trunc(a2), al2 = tf32_trunc(a2 - ah2);
            float ah3 = tf32_trunc(a3), al3 = tf32_trunc(a3 - ah3);
            #pragma unroll
            for (int nt = 0; nt < 2; ++nt) {
                const int bcol = bn0 + nt * 8 + gid;
                float b0 = Bs[cur][ka + tig][bcol];
                float b1 = Bs[cur][ka + tig + 4][bcol];
                float bh0 = tf32_trunc(b0), bl0 = tf32_trunc(b0 - bh0);
                float bh1 = tf32_trunc(b1), bl1 = tf32_trunc(b1 - bh1);
                mma_tf32(acc[nt], ah0, ah1, ah2, ah3, bh0, bh1);
                mma_tf32(acc[nt], ah0, ah1, ah2, ah3, bl0, bl1);
                mma_tf32(acc[nt], al0, al1, al2, al3, bh0, bh1);
            }
        }

        if (s + 1 < NS) {
            const int nb = cur ^ 1;
            if (athr) {
                As[nb][akk + 0][arow] = av2.x; As[nb][akk + 1][arow] = av2.y;
                As[nb][akk + 2][arow] = av2.z; As[nb][akk + 3][arow] = av2.w;
            }
            *reinterpret_cast<float4*>(&Bs[nb][bk][bn]) = bv2;
        }
        __syncthreads();
    }

    const int r0 = mt * 32 + am + gid;
    const int r1 = r0 + 8;
    int ridx0 = 0, ridx1 = 0;
    const bool v0 = (r0 < cnt), v1 = (r1 < cnt);
    if (v0) ridx0 = g_idx[c * BMAX + r0];
    if (v1) ridx1 = g_idx[c * BMAX + r1];

    #pragma unroll
    for (int nt = 0; nt < 2; ++nt) {
        const int cn = bn0 + nt * 8 + 2 * tig;
        const float bb0 = bias[colbase + cn];
        const float bb1 = bias[colbase + cn + 1];
        if (v0) {
            float2 o;
            o.x = fmaxf(acc[nt][0] + bb0, 0.f);
            o.y = fmaxf(acc[nt][1] + bb1, 0.f);
            *reinterpret_cast<float2*>(&g_feature[(size_t)ridx0 * EDIM + outcol + cn]) = o;
        }
        if (v1) {
            float2 o;
            o.x = fmaxf(acc[nt][2] + bb0, 0.f);
            o.y = fmaxf(acc[nt][3] + bb1, 0.f);
            *reinterpret_cast<float2*>(&g_feature[(size_t)ridx1 * EDIM + outcol + cn]) = o;
        }
    }
}

// ---------------------------------------------------------------------------
// shared MLP: [B,768]@[768,384] -> g_feature[:, 0:384]  (grid: 6 x mtiles)
// ---------------------------------------------------------------------------
__global__ void __launch_bounds__(256) shared_mlp_kernel(
    const float* __restrict__ pooled,
    const float* __restrict__ Wsh, const float* __restrict__ bsh, int B)
{
    __shared__ float As[2][16][68];
    __shared__ float Bs[2][16][68];
    mma_gemm64_tile(pooled, EDIM, Wsh, HDIM, bsh, g_feature, EDIM,
                    B, EDIM, blockIdx.y, blockIdx.x * 64, As, Bs);
}

// ---------------------------------------------------------------------------
// domain1: [B,384]@[384,384] -> g_hdom   (grid: 6 x mtiles)
// ---------------------------------------------------------------------------
__global__ void __launch_bounds__(256) dom1_kernel(
    const float* __restrict__ Wdo1, const float* __restrict__ bdo1, int B)
{
    __shared__ float As[2][16][68];
    __shared__ float Bs[2][16][68];
    mma_gemm64_tile(g_feature, EDIM, Wdo1, HDIM, bdo1, g_hdom, HDIM,
                    B, HDIM, blockIdx.y, blockIdx.x * 64, As, Bs);
}

// ---------------------------------------------------------------------------
// domain2: warp per sample, dp = hdom @ Wdo2 + bdo2 (N=9)
// ---------------------------------------------------------------------------
__global__ void __launch_bounds__(256) dom2_kernel(
    const float* __restrict__ Wdo2, const float* __restrict__ bdo2,
    float* __restrict__ dp, int B)
{
    const int sample = (blockIdx.x * 256 + threadIdx.x) >> 5;
    const int lane = threadIdx.x & 31;
    if (sample >= B) return;
    const float* h = g_hdom + (size_t)sample * HDIM;
    float a[NDOM];
    #pragma unroll
    for (int j = 0; j < NDOM; ++j) a[j] = 0.f;
    #pragma unroll
    for (int i = 0; i < 3; ++i) {
        const int k = (lane + 32 * i) * 4;
        float4 hv = *reinterpret_cast<const float4*>(h + k);
        float hh[4] = {hv.x, hv.y, hv.z, hv.w};
        #pragma unroll
        for (int q = 0; q < 4; ++q) {
            const float* wrow = Wdo2 + (k + q) * NDOM;
            #pragma unroll
            for (int j = 0; j < NDOM; ++j) a[j] += hh[q] * wrow[j];
        }
    }
    #pragma unroll
    for (int j = 0; j < NDOM; ++j) {
        #pragma unroll
        for (int o = 16; o; o >>= 1) a[j] += __shfl_xor_sync(0xffffffffu, a[j], o);
    }
    if (lane == 0) {
        #pragma unroll
        for (int j = 0; j < NDOM; ++j)
            dp[(size_t)sample * NDOM + j] = a[j] + bdo2[j];
    }
}

// ---------------------------------------------------------------------------
// dec1 + cls: blocks [0,32) = dec1 mma tiles; rest = cls warp/sample.
// ---------------------------------------------------------------------------
#define DC_DEC1 32
__global__ void __launch_bounds__(256) dec1cls_kernel(
    const float* __restrict__ Wd1, const float* __restrict__ bd1,
    const float* __restrict__ Wc, const float* __restrict__ bc,
    float* __restrict__ out, int B)
{
    __shared__ float As[2][16][68];
    __shared__ float Bs[2][16][68];
    const int bx = blockIdx.x;

    if (bx < DC_DEC1) {
        mma_gemm64_tile(g_feature, EDIM, Wd1, 64, bd1, g_h1, 64, B, EDIM,
                        bx, 0, As, Bs);
    } else {
        const int sample = (bx - DC_DEC1) * 8 + (threadIdx.x >> 5);
        const int lane = threadIdx.x & 31;
        if (sample < B) {
            const float4* f = reinterpret_cast<const float4*>(g_feature + (size_t)sample * EDIM);
            const float4* wc = reinterpret_cast<const float4*>(Wc);
            float acc = 0.f;
            #pragma unroll
            for (int i = 0; i < 6; ++i) {
                float4 a = f[lane + 32 * i], ww = wc[lane + 32 * i];
                acc += a.x * ww.x + a.y * ww.y + a.z * ww.z + a.w * ww.w;
            }
            #pragma unroll
            for (int o = 16; o; o >>= 1) acc += __shfl_xor_sync(0xffffffffu, acc, o);
            if (lane == 0) out[sample] = 1.f / (1.f + __expf(-(acc + bc[0])));
        }
    }
}

// ---------------------------------------------------------------------------
// dec2: [B,64]@[64,768] -> rec   (grid: 12 coltiles x 32 mtiles = 384)
// ---------------------------------------------------------------------------
__global__ void __launch_bounds__(256) dec2_kernel(
    const float* __restrict__ Wd2, const float* __restrict__ bd2,
    float* __restrict__ rec, int B)
{
    __shared__ float As[2][16][68];
    __shared__ float Bs[2][16][68];
    mma_gemm64_tile(g_h1, 64, Wd2, EDIM, bd2, rec, EDIM, B, 64,
                    blockIdx.x / 12, (blockIdx.x % 12) * 64, As, Bs);
}

// ---------------------------------------------------------------------------
extern "C" void kernel_launch(void* const* d_in, const int* in_sizes, int n_in,
                              void* d_out, int out_size)
{
    const float* bert     = (const float*)d_in[0];
    const int*   masks    = (const int*)d_in[1];
    const int*   category = (const int*)d_in[2];
    const float* att_w = (const float*)d_in[4];
    const float* att_b = (const float*)d_in[5];
    const float* Wsh = (const float*)d_in[6];  const float* bsh = (const float*)d_in[7];
    const float* Wsp = (const float*)d_in[8];  const float* bsp = (const float*)d_in[9];
    const float* Wd1 = (const float*)d_in[10]; const float* bd1 = (const float*)d_in[11];
    const float* Wd2 = (const float*)d_in[12]; const float* bd2 = (const float*)d_in[13];
    const float* Wc  = (const float*)d_in[14]; const float* bc  = (const float*)d_in[15];
    const float* Wdo1 = (const float*)d_in[16]; const float* bdo1 = (const float*)d_in[17];
    const float* Wdo2 = (const float*)d_in[18]; const float* bdo2 = (const float*)d_in[19];

    const int B = in_sizes[2];

    float* out    = (float*)d_out;
    float* rec    = out + B;
    float* pooled = rec + (size_t)B * EDIM;
    float* dp     = pooled + (size_t)B * EDIM;

    // one-time stream/event creation (first call is the uncaptured
    // correctness run; capture-time calls reuse these handles)
    static bool s_init = false;
    static cudaStream_t s1;
    static cudaEvent_t evPool, evSh, evEnd;
    if (!s_init) {
        cudaStreamCreateWithFlags(&s1, cudaStreamNonBlocking);
        cudaEventCreateWithFlags(&evPool, cudaEventDisableTiming);
        cudaEventCreateWithFlags(&evSh, cudaEventDisableTiming);
        cudaEventCreateWithFlags(&evEnd, cudaEventDisableTiming);
        s_init = true;
    }

    const int mt64 = (B + 63) / 64;    // 64-row tiles
    const int mt32 = (B + 31) / 32;    // 32-row tiles (expert)

    // ---- main stream: routing + pool ----
    zero_counts_kernel<<<1, 16>>>();
    scatter_kernel<<<(B + 255) / 256, 256>>>(category, B);
    pool_kernel<<<B, 192>>>(bert, masks, att_w, att_b, pooled);
    cudaEventRecord(evPool, 0);

    // ---- side stream: shared MLP -> domain1 -> domain2 ----
    cudaStreamWaitEvent(s1, evPool, 0);
    shared_mlp_kernel<<<dim3(HDIM / 64, mt64), 256, 0, s1>>>(pooled, Wsh, bsh, B);
    cudaEventRecord(evSh, s1);
    dom1_kernel<<<dim3(HDIM / 64, mt64), 256, 0, s1>>>(Wdo1, bdo1, B);
    dom2_kernel<<<(B * 32 + 255) / 256, 256, 0, s1>>>(Wdo2, bdo2, dp, B);
    cudaEventRecord(evEnd, s1);

    // ---- main stream: specific experts (concurrent with side stream) ----
    expert_mma_kernel<<<dim3(HDIM / 64, mt32, NDOM), 256>>>(pooled, Wsp, bsp);

    // dec1+cls need shared (side stream) + specific (this stream)
    cudaStreamWaitEvent(0, evSh, 0);
    dec1cls_kernel<<<DC_DEC1 + (B + 7) / 8, 256>>>(Wd1, bd1, Wc, bc, out, B);
    dec2_kernel<<<12 * mt64, 256>>>(Wd2, bd2, rec, B);

    // join side stream before returning (capture requires joined fork)
    cudaStreamWaitEvent(0, evEnd, 0);
}